// round 14
// baseline (speedup 1.0000x reference)
#include <cuda_runtime.h>
#include <cuda_fp16.h>
#include <mma.h>
#include <math.h>
#include <stdint.h>

using namespace nvcuda;

// Problem constants
#define Bc     16
#define L1c    512
#define L2c    512
#define Dc     512
#define Hc     8
#define INNERc 1024
#define HDc    128
#define DCc    640   // D + HD

// ---------------- fp16 hi/lo pair scratch (static device globals) -------------
__device__ __align__(256) __half g_Ph [(size_t)Bc*L1c*Dc];
__device__ __align__(256) __half g_Pl [(size_t)Bc*L1c*Dc];
__device__ __align__(256) __half g_Sh [(size_t)Bc*L2c*Dc];
__device__ __align__(256) __half g_Sl [(size_t)Bc*L2c*Dc];
__device__ __align__(256) __half g_WaffTh[(size_t)Hc*Dc*Dc];
__device__ __align__(256) __half g_WaffTl[(size_t)Hc*Dc*Dc];
__device__ __align__(256) __half g_WpTh[(size_t)INNERc*Dc];
__device__ __align__(256) __half g_WpTl[(size_t)INNERc*Dc];
__device__ __align__(256) __half g_WsTh[(size_t)INNERc*Dc];
__device__ __align__(256) __half g_WsTl[(size_t)INNERc*Dc];
__device__ __align__(256) __half g_WfpTh[(size_t)Dc*DCc];
__device__ __align__(256) __half g_WfsTh[(size_t)Dc*DCc];
__device__ __align__(256) __half g_Th  [(size_t)Bc*Hc*L1c*Dc];
__device__ __align__(256) __half g_Tl  [(size_t)Bc*Hc*L1c*Dc];
__device__ __align__(256) __half g_affh [(size_t)Bc*Hc*L1c*L2c];
__device__ __align__(256) __half g_affTh[(size_t)Bc*Hc*L2c*L1c];
__device__ __align__(256) __half g_PPTh[(size_t)Bc*INNERc*L1c];
__device__ __align__(256) __half g_PSTh[(size_t)Bc*INNERc*L2c];
__device__ __align__(256) float  g_wp [(size_t)Bc*Hc*L2c*HDc];
__device__ __align__(256) float  g_ws [(size_t)Bc*Hc*L1c*HDc];
__device__ __align__(256) __half g_poolph[(size_t)Bc*L2c*HDc];
__device__ __align__(256) __half g_poolsh[(size_t)Bc*L1c*HDc];

// ---------------- helpers -----------------------------------------------------
__device__ __forceinline__ uint32_t smem_u32(const void* p) {
    uint32_t a;
    asm("{ .reg .u64 t; cvta.to.shared.u64 t, %1; cvt.u32.u64 %0, t; }" : "=r"(a) : "l"(p));
    return a;
}
__device__ __forceinline__ void cpa16(uint32_t dst, const void* src) {
    asm volatile("cp.async.cg.shared.global [%0], [%1], 16;" :: "r"(dst), "l"(src));
}
__device__ __forceinline__ void cpa_commit() { asm volatile("cp.async.commit_group;" ::: "memory"); }
template<int N>
__device__ __forceinline__ void cpa_wait() {
    asm volatile("cp.async.wait_group %0;" :: "n"(N) : "memory");
}

__device__ __forceinline__ void split2(float x, __half& h, __half& l) {
    h = __float2half_rn(x);
    l = __float2half_rn(x - __half2float(h));
}

#define CSLD 132   // f32 epilogue smem stride
#define NTHR 128   // 4 warps, 2x2 of 64x64 warp tiles

// ---- staging: global fp16 rows -> smem tile (128 rows x KCH halves) ----------
// row stride TLD = KCH+8 halves: 16B-aligned rows, bank-clean for LDSM.
template<int KCH, int MODE>
__device__ __forceinline__ void stage16(const __half* __restrict__ G, int ld,
                                        const __half* __restrict__ pool,
                                        int rb, int k0, uint32_t dst) {
    constexpr int RPR = KCH / 8;
    constexpr int IT  = 128 * RPR / NTHR;
    const int tid = threadIdx.x;
    #pragma unroll
    for (int r = 0; r < IT; r++) {
        int idx = r * NTHR + tid;
        int m   = idx / RPR;
        int kq  = (idx % RPR) * 8;
        const __half* src;
        if (MODE == 0) {
            src = G + (size_t)(rb + m) * ld + k0 + kq;
        } else {
            int gk = k0 + kq;
            src = (gk < Dc) ? G    + (size_t)(rb + m) * Dc  + gk
                            : pool + (size_t)(rb + m) * HDc + (gk - Dc);
        }
        cpa16(dst + m * ((KCH + 8) * 2) + kq * 2, src);
    }
}

typedef wmma::fragment<wmma::matrix_a, 16, 16, 16, __half, wmma::row_major> FragA;
typedef wmma::fragment<wmma::matrix_b, 16, 16, 16, __half, wmma::col_major> FragB;
typedef wmma::fragment<wmma::accumulator, 16, 16, 16, float> FragC;

// ---------------- core GEMM: NSTAGE-deep cp.async pipeline, 64x64 warp tiles ---
// PASSES 3: AhBh+AlBh+AhBl; 2: AhBh+AlBh; 1: AhBh.
// Pipeline: NSTAGE buffers, prologue stages NSTAGE-1 chunks, steady state waits
// with depth NSTAGE-2 (staging gets NSTAGE-2 chunk-times of latency cover).
// Buffer (c+NSTAGE-1)%NSTAGE is free at iter c: last read by mma(c-1), which
// precedes this iteration's barrier in every warp's program order.
template<int PASSES, int KCH, int NSTAGE, int AMODE, int EPI>
__device__ __forceinline__ void gemm_core(
    const __half* __restrict__ Ah_g, const __half* __restrict__ Al_g,
    const __half* __restrict__ aph,  const __half* __restrict__ apl,
    const __half* __restrict__ Bh_g, const __half* __restrict__ Bl_g,
    float* __restrict__ Cf, __half* __restrict__ Ch, __half* __restrict__ Cl,
    __half* __restrict__ CTh, int ldct,
    int K, int lda, int ldb, int ldc,
    const float* __restrict__ rs, const float* __restrict__ cs,
    const float* __restrict__ bias)
{
    constexpr int TLD   = KCH + 8;
    constexpr int TILEB = 128 * TLD * 2;
    constexpr int NT    = PASSES + 1;
    constexpr int BUFB  = NT * TILEB;
    constexpr int BOFF  = (PASSES >= 2) ? 2 : 1;

    extern __shared__ char smc[];
    const uint32_t smb = smem_u32(smc);

    const int tid  = threadIdx.x;
    const int wid  = tid >> 5;
    const int lane = tid & 31;
    const int wm   = wid & 1;
    const int wn   = wid >> 1;
    const int row0 = blockIdx.y * 128;
    const int col0 = blockIdx.x * 128;

    FragC acc[4][4];
    #pragma unroll
    for (int i = 0; i < 4; i++)
        #pragma unroll
        for (int j = 0; j < 4; j++) wmma::fill_fragment(acc[i][j], 0.0f);

    const int NCH = K / KCH;

    // prologue: stage chunks 0..NSTAGE-2
    #pragma unroll
    for (int p = 0; p < NSTAGE - 1; p++) {
        uint32_t bb = smb + p * BUFB;
        int k0 = p * KCH;
        stage16<KCH, AMODE>(Ah_g, lda, aph, row0, k0, bb);
        if (PASSES >= 2)
            stage16<KCH, AMODE>(Al_g, lda, apl, row0, k0, bb + TILEB);
        stage16<KCH, 0>(Bh_g, ldb, nullptr, col0, k0, bb + BOFF * TILEB);
        if (PASSES == 3)
            stage16<KCH, 0>(Bl_g, ldb, nullptr, col0, k0, bb + 3 * TILEB);
        cpa_commit();
    }

    int buf = 0, nbuf = NSTAGE - 1;
    for (int c = 0; c < NCH; c++) {
        cpa_wait<NSTAGE - 2>();   // chunk c landed (up to NSTAGE-2 still in flight)
        __syncthreads();          // publish; mma(c-1) done in all warps -> nbuf free
        if (c + NSTAGE - 1 < NCH) {
            uint32_t bb = smb + nbuf * BUFB;
            int k0 = (c + NSTAGE - 1) * KCH;
            stage16<KCH, AMODE>(Ah_g, lda, aph, row0, k0, bb);
            if (PASSES >= 2)
                stage16<KCH, AMODE>(Al_g, lda, apl, row0, k0, bb + TILEB);
            stage16<KCH, 0>(Bh_g, ldb, nullptr, col0, k0, bb + BOFF * TILEB);
            if (PASSES == 3)
                stage16<KCH, 0>(Bl_g, ldb, nullptr, col0, k0, bb + 3 * TILEB);
        }
        cpa_commit();             // one group per iteration (may be empty)

        const __half* Ahs = (const __half*)(smc + buf * BUFB);
        const __half* Als = Ahs + TILEB / 2;
        const __half* Bhs = Ahs + BOFF * (TILEB / 2);
        const __half* Bls = Ahs + 3 * (TILEB / 2);

        #pragma unroll
        for (int ks = 0; ks < KCH / 16; ks++) {
            FragA fah[4], fal[4];
            #pragma unroll
            for (int ti = 0; ti < 4; ti++) {
                int ro = (wm * 64 + ti * 16) * TLD + ks * 16;
                wmma::load_matrix_sync(fah[ti], Ahs + ro, TLD);
                if (PASSES >= 2)
                    wmma::load_matrix_sync(fal[ti], Als + ro, TLD);
            }
            #pragma unroll
            for (int tj = 0; tj < 4; tj++) {
                int co = (wn * 64 + tj * 16) * TLD + ks * 16;
                {
                    FragB fbh;
                    wmma::load_matrix_sync(fbh, Bhs + co, TLD);
                    #pragma unroll
                    for (int ti = 0; ti < 4; ti++) {
                        wmma::mma_sync(acc[ti][tj], fah[ti], fbh, acc[ti][tj]);
                        if (PASSES >= 2)
                            wmma::mma_sync(acc[ti][tj], fal[ti], fbh, acc[ti][tj]);
                    }
                }
                if (PASSES == 3) {
                    FragB fbl;
                    wmma::load_matrix_sync(fbl, Bls + co, TLD);
                    #pragma unroll
                    for (int ti = 0; ti < 4; ti++)
                        wmma::mma_sync(acc[ti][tj], fah[ti], fbl, acc[ti][tj]);
                }
            }
        }
        buf  = (buf  + 1 == NSTAGE) ? 0 : buf  + 1;
        nbuf = (nbuf + 1 == NSTAGE) ? 0 : nbuf + 1;
    }
    __syncthreads();

    // ---------------- epilogue through smem -----------------------------------
    float* Cs = (float*)smc;
    #pragma unroll
    for (int ti = 0; ti < 4; ti++)
        #pragma unroll
        for (int tj = 0; tj < 4; tj++)
            wmma::store_matrix_sync(Cs + (wm * 64 + ti * 16) * CSLD + wn * 64 + tj * 16,
                                    acc[ti][tj], CSLD, wmma::mem_row_major);
    __syncthreads();

    #pragma unroll
    for (int it = 0; it < 32; it++) {
        int row = it * 4 + wid;
        float4 v = *(float4*)(Cs + row * CSLD + lane * 4);
        if (EPI == 0) {
            __half h0, h1, h2, h3, l0, l1, l2, l3;
            split2(v.x, h0, l0); split2(v.y, h1, l1);
            split2(v.z, h2, l2); split2(v.w, h3, l3);
            size_t off = (size_t)(row0 + row) * ldc + col0 + lane * 4;
            *(__half2*)(Ch + off)     = __halves2half2(h0, h1);
            *(__half2*)(Ch + off + 2) = __halves2half2(h2, h3);
            *(__half2*)(Cl + off)     = __halves2half2(l0, l1);
            *(__half2*)(Cl + off + 2) = __halves2half2(l2, l3);
        } else if (EPI == 1) {
            float rm = rs[row0 + row];
            v.x = tanhf(v.x) * rm * cs[col0 + lane * 4 + 0];
            v.y = tanhf(v.y) * rm * cs[col0 + lane * 4 + 1];
            v.z = tanhf(v.z) * rm * cs[col0 + lane * 4 + 2];
            v.w = tanhf(v.w) * rm * cs[col0 + lane * 4 + 3];
            *(float4*)(Cs + row * CSLD + lane * 4) = v;   // for transposed pass
            size_t off = (size_t)(row0 + row) * ldc + col0 + lane * 4;
            *(__half2*)(Ch + off)     = __halves2half2(__float2half_rn(v.x), __float2half_rn(v.y));
            *(__half2*)(Ch + off + 2) = __halves2half2(__float2half_rn(v.z), __float2half_rn(v.w));
        } else if (EPI == 2) {
            v.x = fmaxf(v.x, 0.f); v.y = fmaxf(v.y, 0.f);
            v.z = fmaxf(v.z, 0.f); v.w = fmaxf(v.w, 0.f);
            *(float4*)(Cf + (size_t)(row0 + row) * ldc + col0 + lane * 4) = v;
        } else if (EPI == 3) {
            v.x = fmaxf(v.x + bias[col0 + lane * 4 + 0], 0.f);
            v.y = fmaxf(v.y + bias[col0 + lane * 4 + 1], 0.f);
            v.z = fmaxf(v.z + bias[col0 + lane * 4 + 2], 0.f);
            v.w = fmaxf(v.w + bias[col0 + lane * 4 + 3], 0.f);
            *(float4*)(Cf + (size_t)(row0 + row) * ldc + col0 + lane * 4) = v;
        } else {   // EPI == 4: hi-only write
            size_t off = (size_t)(row0 + row) * ldc + col0 + lane * 4;
            *(__half2*)(Ch + off)     = __halves2half2(__float2half_rn(v.x), __float2half_rn(v.y));
            *(__half2*)(Ch + off + 2) = __halves2half2(__float2half_rn(v.z), __float2half_rn(v.w));
        }
    }

    if (EPI == 1) {
        __syncthreads();
        #pragma unroll
        for (int ct = 0; ct < 32; ct++) {
            int col = ct * 4 + wid;
            #pragma unroll
            for (int cc = 0; cc < 4; cc++) {
                int r = cc * 32 + lane;
                float x = Cs[r * CSLD + col];
                CTh[(size_t)(col0 + col) * ldct + row0 + r] = __float2half_rn(x);
            }
        }
    }
}

// smem sizes
#define SM_P3 (4 * 4 * (128 * 24 * 2))   // 98304  (3-pass, KCH=16, 4-stage, 2 CTA/SM)
#define SM_P2 (2 * 3 * (128 * 72 * 2))   // 110592 (2-pass, KCH=64, 2-stage, 2 CTA/SM)
#define SM_P1 (3 * 2 * (128 * 72 * 2))   // 110592 (1-pass, KCH=64, 3-stage, 2 CTA/SM)

// ---------------- GEMM kernels ------------------------------------------------
__global__ __launch_bounds__(NTHR, 2) void k_pw() {
    int bh = blockIdx.z;
    gemm_core<3, 16, 4, 0, 0>(g_Ph + (size_t)(bh >> 3) * L1c * Dc,
                              g_Pl + (size_t)(bh >> 3) * L1c * Dc, nullptr, nullptr,
                              g_WaffTh + (size_t)(bh & 7) * Dc * Dc,
                              g_WaffTl + (size_t)(bh & 7) * Dc * Dc,
                              nullptr, g_Th + (size_t)bh * L1c * Dc,
                              g_Tl + (size_t)bh * L1c * Dc,
                              nullptr, 0,
                              Dc, Dc, Dc, Dc, nullptr, nullptr, nullptr);
}
__global__ __launch_bounds__(NTHR, 2) void k_aff(const float* __restrict__ pm,
                                                 const float* __restrict__ sm_) {
    int bh = blockIdx.z, b = bh >> 3;
    gemm_core<3, 16, 4, 0, 1>(g_Th + (size_t)bh * L1c * Dc,
                              g_Tl + (size_t)bh * L1c * Dc, nullptr, nullptr,
                              g_Sh + (size_t)b * L2c * Dc,
                              g_Sl + (size_t)b * L2c * Dc,
                              nullptr,
                              g_affh + (size_t)bh * L1c * L2c, nullptr,
                              g_affTh + (size_t)bh * L2c * L1c, L1c,
                              Dc, Dc, Dc, L2c,
                              pm + b * L1c, sm_ + b * L2c, nullptr);
}
__global__ __launch_bounds__(NTHR, 2) void k_proj() {
    int b = blockIdx.z >> 1, sel = blockIdx.z & 1;
    const __half* Wh = sel ? g_WsTh : g_WpTh;
    const __half* Wl = sel ? g_WsTl : g_WpTl;
    const __half* Xh = (sel ? g_Sh : g_Ph) + (size_t)b * L1c * Dc;
    __half* Oh = (sel ? g_PSTh : g_PPTh) + (size_t)b * INNERc * L1c;
    gemm_core<2, 64, 2, 0, 4>(Wh, Wl, nullptr, nullptr, Xh, nullptr,
                              nullptr, Oh, nullptr, nullptr, 0,
                              Dc, Dc, Dc, L1c, nullptr, nullptr, nullptr);
}
__global__ __launch_bounds__(NTHR, 2) void k_wpws() {
    int bh = blockIdx.z >> 1, sel = blockIdx.z & 1;
    int b = bh >> 3, h = bh & 7;
    const __half *Ah_, *Bh_;
    float* Cf;
    if (sel == 0) {
        Ah_ = g_affTh + (size_t)bh * L2c * L1c;
        Bh_ = g_PPTh + (size_t)b * INNERc * L1c + (size_t)h * HDc * L1c;
        Cf  = g_wp + (size_t)bh * L2c * HDc;
    } else {
        Ah_ = g_affh + (size_t)bh * L1c * L2c;
        Bh_ = g_PSTh + (size_t)b * INNERc * L2c + (size_t)h * HDc * L2c;
        Cf  = g_ws + (size_t)bh * L1c * HDc;
    }
    gemm_core<1, 64, 3, 0, 2>(Ah_, nullptr, nullptr, nullptr, Bh_, nullptr,
                              Cf, nullptr, nullptr, nullptr, 0,
                              L1c, L1c, L1c, HDc, nullptr, nullptr, nullptr);
}
__global__ __launch_bounds__(NTHR, 2) void k_ffn(const float* __restrict__ bfp,
                                                 const float* __restrict__ bfs,
                                                 float* __restrict__ Op,
                                                 float* __restrict__ Os) {
    int b = blockIdx.z >> 1, sel = blockIdx.z & 1;
    const __half* Xh = (sel ? g_Sh : g_Ph) + (size_t)b * L1c * Dc;
    const __half* ph = (sel ? g_poolph : g_poolsh) + (size_t)b * L1c * HDc;
    const __half* Wh = sel ? g_WfsTh : g_WfpTh;
    const float* bias = sel ? bfs : bfp;
    float* O = (sel ? Os : Op) + (size_t)b * L1c * Dc;
    gemm_core<1, 64, 3, 1, 3>(Xh, nullptr, ph, nullptr, Wh, nullptr,
                              O, nullptr, nullptr, nullptr, 0,
                              DCc, Dc, DCc, Dc, nullptr, nullptr, bias);
}

// ---------------- conversion kernels ------------------------------------------
__global__ void k_split2(const float* __restrict__ X0, __half* __restrict__ H0, __half* __restrict__ L0,
                         const float* __restrict__ X1, __half* __restrict__ H1, __half* __restrict__ L1,
                         int n) {
    const float* X = blockIdx.y ? X1 : X0;
    __half* H = blockIdx.y ? H1 : H0;
    __half* L = blockIdx.y ? L1 : L0;
    int i = (blockIdx.x * blockDim.x + threadIdx.x) * 4;
    if (i >= n) return;
    float4 v = *(const float4*)(X + i);
    __half h0, h1, h2, h3, l0, l1, l2, l3;
    split2(v.x, h0, l0); split2(v.y, h1, l1);
    split2(v.z, h2, l2); split2(v.w, h3, l3);
    *(__half2*)(H + i)     = __halves2half2(h0, h1);
    *(__half2*)(H + i + 2) = __halves2half2(h2, h3);
    *(__half2*)(L + i)     = __halves2half2(l0, l1);
    *(__half2*)(L + i + 2) = __halves2half2(l2, l3);
}

__global__ void k_splitT(const float* __restrict__ X,
                         __half* __restrict__ H, __half* __restrict__ L,
                         int R, int C) {
    __shared__ float t[32][33];
    int z = blockIdx.z;
    int x0 = blockIdx.x * 32;
    int y0 = blockIdx.y * 32;
    const float* Xz = X + (size_t)z * R * C;
    #pragma unroll
    for (int i = 0; i < 4; i++) {
        int r = y0 + threadIdx.y * 4 + i;
        t[threadIdx.y * 4 + i][threadIdx.x] = Xz[(size_t)r * C + x0 + threadIdx.x];
    }
    __syncthreads();
    size_t zb = (size_t)z * R * C;
    #pragma unroll
    for (int i = 0; i < 4; i++) {
        int oc = x0 + threadIdx.y * 4 + i;
        float v = t[threadIdx.x][threadIdx.y * 4 + i];
        __half h, l;
        split2(v, h, l);
        H[zb + (size_t)oc * R + y0 + threadIdx.x] = h;
        L[zb + (size_t)oc * R + y0 + threadIdx.x] = l;
    }
}

__global__ void k_splitT4(const float* __restrict__ Wp,  __half* __restrict__ WpH,  __half* __restrict__ WpL,
                          const float* __restrict__ Ws,  __half* __restrict__ WsH,  __half* __restrict__ WsL,
                          const float* __restrict__ Wfp, __half* __restrict__ WfpH,
                          const float* __restrict__ Wfs, __half* __restrict__ WfsH) {
    __shared__ float t[32][33];
    int z = blockIdx.z;
    int R = (z < 2) ? Dc : DCc;
    int C = (z < 2) ? INNERc : Dc;
    if ((int)blockIdx.x * 32 >= C || (int)blockIdx.y * 32 >= R) return;
    const float* X = (z == 0) ? Wp : (z == 1) ? Ws : (z == 2) ? Wfp : Wfs;
    __half* H = (z == 0) ? WpH : (z == 1) ? WsH : (z == 2) ? WfpH : WfsH;
    __half* L = (z == 0) ? WpL : (z == 1) ? WsL : nullptr;
    int x0 = blockIdx.x * 32;
    int y0 = blockIdx.y * 32;
    #pragma unroll
    for (int i = 0; i < 4; i++) {
        int r = y0 + threadIdx.y * 4 + i;
        t[threadIdx.y * 4 + i][threadIdx.x] = X[(size_t)r * C + x0 + threadIdx.x];
    }
    __syncthreads();
    #pragma unroll
    for (int i = 0; i < 4; i++) {
        int oc = x0 + threadIdx.y * 4 + i;
        float v = t[threadIdx.x][threadIdx.y * 4 + i];
        __half h, l;
        split2(v, h, l);
        H[(size_t)oc * R + y0 + threadIdx.x] = h;
        if (z < 2) L[(size_t)oc * R + y0 + threadIdx.x] = l;
    }
}

// ---------------- merged pools (hi only) ---------------------------------------
__global__ void k_pool2() {
    int idx = blockIdx.x * blockDim.x + threadIdx.x;
    const int tot = Bc * L2c * HDc;
    if (idx >= tot) return;
    int b = idx / (L2c * HDc);
    int r = idx - b * (L2c * HDc);
    if (blockIdx.y == 0) {
        float m = g_wp[((size_t)b * Hc) * L2c * HDc + r];
        #pragma unroll
        for (int h = 1; h < Hc; h++)
            m = fmaxf(m, g_wp[((size_t)(b * Hc + h)) * L2c * HDc + r]);
        g_poolph[idx] = __float2half_rn(m);
    } else {
        float m = g_ws[((size_t)b * Hc) * L1c * HDc + r];
        #pragma unroll
        for (int h = 1; h < Hc; h++)
            m = fmaxf(m, g_ws[((size_t)(b * Hc + h)) * L1c * HDc + r]);
        g_poolsh[idx] = __float2half_rn(m);
    }
}

// ---------------- launcher -----------------------------------------------------
template<typename T>
static T* sym_addr(const void* sym) {
    void* p = nullptr;
    cudaGetSymbolAddress(&p, sym);
    return (T*)p;
}

extern "C" void kernel_launch(void* const* d_in, const int* in_sizes, int n_in,
                              void* d_out, int out_size) {
    const float* P    = (const float*)d_in[0];
    const float* S    = (const float*)d_in[1];
    const float* pm   = (const float*)d_in[2];
    const float* sm   = (const float*)d_in[3];
    const float* Waff = (const float*)d_in[4];
    const float* Wp   = (const float*)d_in[5];
    const float* Ws   = (const float*)d_in[6];
    const float* Wfp  = (const float*)d_in[7];
    const float* bfp  = (const float*)d_in[8];
    const float* Wfs  = (const float*)d_in[9];
    const float* bfs  = (const float*)d_in[10];

    float* outp = (float*)d_out;
    float* outs = outp + (size_t)Bc * L1c * Dc;

    __half* Ph     = sym_addr<__half>(g_Ph);
    __half* Pl     = sym_addr<__half>(g_Pl);
    __half* Sh     = sym_addr<__half>(g_Sh);
    __half* Sl     = sym_addr<__half>(g_Sl);
    __half* WaffTh = sym_addr<__half>(g_WaffTh);
    __half* WaffTl = sym_addr<__half>(g_WaffTl);
    __half* WpTh   = sym_addr<__half>(g_WpTh);
    __half* WpTl   = sym_addr<__half>(g_WpTl);
    __half* WsTh   = sym_addr<__half>(g_WsTh);
    __half* WsTl   = sym_addr<__half>(g_WsTl);
    __half* WfpTh  = sym_addr<__half>(g_WfpTh);
    __half* WfsTh  = sym_addr<__half>(g_WfsTh);

    cudaFuncSetAttribute(k_pw,   cudaFuncAttributeMaxDynamicSharedMemorySize, SM_P3);
    cudaFuncSetAttribute(k_aff,  cudaFuncAttributeMaxDynamicSharedMemorySize, SM_P3);
    cudaFuncSetAttribute(k_proj, cudaFuncAttributeMaxDynamicSharedMemorySize, SM_P2);
    cudaFuncSetAttribute(k_wpws, cudaFuncAttributeMaxDynamicSharedMemorySize, SM_P1);
    cudaFuncSetAttribute(k_ffn,  cudaFuncAttributeMaxDynamicSharedMemorySize, SM_P1);

    static cudaStream_t s_side = nullptr;
    static cudaEvent_t  ev_fork = nullptr, ev_join = nullptr;
    static int stream_ok = -1;
    if (stream_ok < 0) {
        stream_ok = (cudaStreamCreateWithFlags(&s_side, cudaStreamNonBlocking) == cudaSuccess &&
                     cudaEventCreateWithFlags(&ev_fork, cudaEventDisableTiming) == cudaSuccess &&
                     cudaEventCreateWithFlags(&ev_join, cudaEventDisableTiming) == cudaSuccess) ? 1 : 0;
    }

    dim3 blk(NTHR);

    // ---- main stream: input split, Waff split, pw, aff (aff = launch #4) ----
    {
        int n = Bc * L1c * Dc;
        k_split2<<<dim3(n / 1024, 2), 256>>>(P, Ph, Pl, S, Sh, Sl, n);
    }
    if (stream_ok) cudaEventRecord(ev_fork, 0);

    k_splitT<<<dim3(Dc / 32, Dc / 32, Hc), dim3(32, 8)>>>(Waff, WaffTh, WaffTl, Dc, Dc);
    k_pw  <<<dim3(4, 4, Bc * Hc), blk, SM_P3>>>();
    k_aff <<<dim3(4, 4, Bc * Hc), blk, SM_P3>>>(pm, sm);

    // ---- side stream: weight transposes + proj, concurrent with pw/aff ------
    if (stream_ok) {
        cudaStreamWaitEvent(s_side, ev_fork, 0);
        k_splitT4<<<dim3(INNERc / 32, DCc / 32, 4), dim3(32, 8), 0, s_side>>>(
            Wp, WpTh, WpTl, Ws, WsTh, WsTl, Wfp, WfpTh, Wfs, WfsTh);
        k_proj<<<dim3(4, 8, Bc * 2), blk, SM_P2, s_side>>>();
        cudaEventRecord(ev_join, s_side);
        cudaStreamWaitEvent(0, ev_join, 0);
    } else {
        k_splitT4<<<dim3(INNERc / 32, DCc / 32, 4), dim3(32, 8)>>>(
            Wp, WpTh, WpTl, Ws, WsTh, WsTl, Wfp, WfpTh, Wfs, WfsTh);
        k_proj<<<dim3(4, 8, Bc * 2), blk, SM_P2>>>();
    }

    // ---- joined: wpws -> pools -> ffn ----------------------------------------
    k_wpws<<<dim3(1, 4, Bc * Hc * 2), blk, SM_P1>>>();

    { int tot = Bc * L2c * HDc; k_pool2<<<dim3((tot + 255) / 256, 2), 256>>>(); }

    k_ffn <<<dim3(4, 4, Bc * 2), blk, SM_P1>>>(bfp, bfs, outp, outs);
}

// round 15
// speedup vs baseline: 1.0850x; 1.0850x over previous
#include <cuda_runtime.h>
#include <cuda_fp16.h>
#include <mma.h>
#include <math.h>
#include <stdint.h>

using namespace nvcuda;

// Problem constants
#define Bc     16
#define L1c    512
#define L2c    512
#define Dc     512
#define Hc     8
#define INNERc 1024
#define HDc    128
#define DCc    640   // D + HD

// ---------------- fp16 hi/lo pair scratch (static device globals) -------------
__device__ __align__(256) __half g_Ph [(size_t)Bc*L1c*Dc];
__device__ __align__(256) __half g_Pl [(size_t)Bc*L1c*Dc];
__device__ __align__(256) __half g_Sh [(size_t)Bc*L2c*Dc];
__device__ __align__(256) __half g_Sl [(size_t)Bc*L2c*Dc];
__device__ __align__(256) __half g_WaffTh[(size_t)Hc*Dc*Dc];
__device__ __align__(256) __half g_WaffTl[(size_t)Hc*Dc*Dc];
__device__ __align__(256) __half g_WpTh[(size_t)INNERc*Dc];
__device__ __align__(256) __half g_WpTl[(size_t)INNERc*Dc];
__device__ __align__(256) __half g_WsTh[(size_t)INNERc*Dc];
__device__ __align__(256) __half g_WsTl[(size_t)INNERc*Dc];
__device__ __align__(256) __half g_WfpTh[(size_t)Dc*DCc];
__device__ __align__(256) __half g_WfsTh[(size_t)Dc*DCc];
__device__ __align__(256) __half g_Th  [(size_t)Bc*Hc*L1c*Dc];
__device__ __align__(256) __half g_Tl  [(size_t)Bc*Hc*L1c*Dc];
__device__ __align__(256) __half g_affh [(size_t)Bc*Hc*L1c*L2c];
__device__ __align__(256) __half g_affTh[(size_t)Bc*Hc*L2c*L1c];
__device__ __align__(256) __half g_PPTh[(size_t)Bc*INNERc*L1c];
__device__ __align__(256) __half g_PSTh[(size_t)Bc*INNERc*L2c];
__device__ __align__(256) __half g_wph[(size_t)Bc*Hc*L2c*HDc];
__device__ __align__(256) __half g_wsh[(size_t)Bc*Hc*L1c*HDc];
__device__ __align__(256) __half g_poolph[(size_t)Bc*L2c*HDc];
__device__ __align__(256) __half g_poolsh[(size_t)Bc*L1c*HDc];

// ---------------- helpers -----------------------------------------------------
__device__ __forceinline__ uint32_t smem_u32(const void* p) {
    uint32_t a;
    asm("{ .reg .u64 t; cvta.to.shared.u64 t, %1; cvt.u32.u64 %0, t; }" : "=r"(a) : "l"(p));
    return a;
}
__device__ __forceinline__ void cpa16(uint32_t dst, const void* src) {
    asm volatile("cp.async.cg.shared.global [%0], [%1], 16;" :: "r"(dst), "l"(src));
}
__device__ __forceinline__ void cpa_commit() { asm volatile("cp.async.commit_group;" ::: "memory"); }
__device__ __forceinline__ void cpa_wait0()  { asm volatile("cp.async.wait_group 0;" ::: "memory"); }

__device__ __forceinline__ void split2(float x, __half& h, __half& l) {
    h = __float2half_rn(x);
    l = __float2half_rn(x - __half2float(h));
}

#define CSLD 132   // f32 epilogue smem stride
#define NTHR 128   // 4 warps, 2x2 of 64x64 warp tiles

// ---- staging: global fp16 rows -> smem tile (128 rows x KCH halves) ----------
template<int KCH, int MODE>
__device__ __forceinline__ void stage16(const __half* __restrict__ G, int ld,
                                        const __half* __restrict__ pool,
                                        int rb, int k0, uint32_t dst) {
    constexpr int RPR = KCH / 8;
    constexpr int IT  = 128 * RPR / NTHR;
    const int tid = threadIdx.x;
    #pragma unroll
    for (int r = 0; r < IT; r++) {
        int idx = r * NTHR + tid;
        int m   = idx / RPR;
        int kq  = (idx % RPR) * 8;
        const __half* src;
        if (MODE == 0) {
            src = G + (size_t)(rb + m) * ld + k0 + kq;
        } else {
            int gk = k0 + kq;
            src = (gk < Dc) ? G    + (size_t)(rb + m) * Dc  + gk
                            : pool + (size_t)(rb + m) * HDc + (gk - Dc);
        }
        cpa16(dst + m * ((KCH + 8) * 2) + kq * 2, src);
    }
}

typedef wmma::fragment<wmma::matrix_a, 16, 16, 16, __half, wmma::row_major> FragA;
typedef wmma::fragment<wmma::matrix_b, 16, 16, 16, __half, wmma::col_major> FragB;
typedef wmma::fragment<wmma::accumulator, 16, 16, 16, float> FragC;

// ---------------- core GEMM (round-12 known-good: 2-stage, 1 sync/chunk) -------
// PASSES 3: AhBh+AlBh+AhBl; 2: AhBh+AlBh; 1: AhBh.
// EPI 0: split hi/lo writes.  EPI 1: tanh*rs*cs -> Ch + CTh (hi only).
// EPI 3: relu(+bias) -> f32.  EPI 4: hi-only write.  EPI 5: relu -> fp16 Ch.
template<int PASSES, int KCH, int AMODE, int EPI>
__device__ __forceinline__ void gemm_core(
    const __half* __restrict__ Ah_g, const __half* __restrict__ Al_g,
    const __half* __restrict__ aph,  const __half* __restrict__ apl,
    const __half* __restrict__ Bh_g, const __half* __restrict__ Bl_g,
    float* __restrict__ Cf, __half* __restrict__ Ch, __half* __restrict__ Cl,
    __half* __restrict__ CTh, int ldct,
    int K, int lda, int ldb, int ldc,
    const float* __restrict__ rs, const float* __restrict__ cs,
    const float* __restrict__ bias)
{
    constexpr int TLD   = KCH + 8;
    constexpr int TILEB = 128 * TLD * 2;
    constexpr int NT    = PASSES + 1;
    constexpr int BUFB  = NT * TILEB;
    constexpr int BOFF  = (PASSES >= 2) ? 2 : 1;

    extern __shared__ char smc[];
    const uint32_t smb = smem_u32(smc);

    const int tid  = threadIdx.x;
    const int wid  = tid >> 5;
    const int lane = tid & 31;
    const int wm   = wid & 1;
    const int wn   = wid >> 1;
    const int row0 = blockIdx.y * 128;
    const int col0 = blockIdx.x * 128;

    FragC acc[4][4];
    #pragma unroll
    for (int i = 0; i < 4; i++)
        #pragma unroll
        for (int j = 0; j < 4; j++) wmma::fill_fragment(acc[i][j], 0.0f);

    const int NCH = K / KCH;

    {
        stage16<KCH, AMODE>(Ah_g, lda, aph, row0, 0, smb);
        if (PASSES >= 2)
            stage16<KCH, AMODE>(Al_g, lda, apl, row0, 0, smb + TILEB);
        stage16<KCH, 0>(Bh_g, ldb, nullptr, col0, 0, smb + BOFF * TILEB);
        if (PASSES == 3)
            stage16<KCH, 0>(Bl_g, ldb, nullptr, col0, 0, smb + 3 * TILEB);
        cpa_commit();
    }

    for (int c = 0; c < NCH; c++) {
        cpa_wait0();
        __syncthreads();
        if (c + 1 < NCH) {
            uint32_t nb = smb + ((c + 1) & 1) * BUFB;
            int k0 = (c + 1) * KCH;
            stage16<KCH, AMODE>(Ah_g, lda, aph, row0, k0, nb);
            if (PASSES >= 2)
                stage16<KCH, AMODE>(Al_g, lda, apl, row0, k0, nb + TILEB);
            stage16<KCH, 0>(Bh_g, ldb, nullptr, col0, k0, nb + BOFF * TILEB);
            if (PASSES == 3)
                stage16<KCH, 0>(Bl_g, ldb, nullptr, col0, k0, nb + 3 * TILEB);
            cpa_commit();
        } else {
            cpa_commit();
        }

        const __half* Ahs = (const __half*)(smc + (c & 1) * BUFB);
        const __half* Als = Ahs + TILEB / 2;
        const __half* Bhs = Ahs + BOFF * (TILEB / 2);
        const __half* Bls = Ahs + 3 * (TILEB / 2);

        #pragma unroll
        for (int ks = 0; ks < KCH / 16; ks++) {
            FragA fah[4], fal[4];
            #pragma unroll
            for (int ti = 0; ti < 4; ti++) {
                int ro = (wm * 64 + ti * 16) * TLD + ks * 16;
                wmma::load_matrix_sync(fah[ti], Ahs + ro, TLD);
                if (PASSES >= 2)
                    wmma::load_matrix_sync(fal[ti], Als + ro, TLD);
            }
            #pragma unroll
            for (int tj = 0; tj < 4; tj++) {
                int co = (wn * 64 + tj * 16) * TLD + ks * 16;
                {
                    FragB fbh;
                    wmma::load_matrix_sync(fbh, Bhs + co, TLD);
                    #pragma unroll
                    for (int ti = 0; ti < 4; ti++) {
                        wmma::mma_sync(acc[ti][tj], fah[ti], fbh, acc[ti][tj]);
                        if (PASSES >= 2)
                            wmma::mma_sync(acc[ti][tj], fal[ti], fbh, acc[ti][tj]);
                    }
                }
                if (PASSES == 3) {
                    FragB fbl;
                    wmma::load_matrix_sync(fbl,
                        Bls + co, TLD);
                    #pragma unroll
                    for (int ti = 0; ti < 4; ti++)
                        wmma::mma_sync(acc[ti][tj], fah[ti], fbl, acc[ti][tj]);
                }
            }
        }
    }
    __syncthreads();

    // ---------------- epilogue through smem -----------------------------------
    float* Cs = (float*)smc;
    #pragma unroll
    for (int ti = 0; ti < 4; ti++)
        #pragma unroll
        for (int tj = 0; tj < 4; tj++)
            wmma::store_matrix_sync(Cs + (wm * 64 + ti * 16) * CSLD + wn * 64 + tj * 16,
                                    acc[ti][tj], CSLD, wmma::mem_row_major);
    __syncthreads();

    #pragma unroll
    for (int it = 0; it < 32; it++) {
        int row = it * 4 + wid;
        float4 v = *(float4*)(Cs + row * CSLD + lane * 4);
        if (EPI == 0) {
            __half h0, h1, h2, h3, l0, l1, l2, l3;
            split2(v.x, h0, l0); split2(v.y, h1, l1);
            split2(v.z, h2, l2); split2(v.w, h3, l3);
            size_t off = (size_t)(row0 + row) * ldc + col0 + lane * 4;
            *(__half2*)(Ch + off)     = __halves2half2(h0, h1);
            *(__half2*)(Ch + off + 2) = __halves2half2(h2, h3);
            *(__half2*)(Cl + off)     = __halves2half2(l0, l1);
            *(__half2*)(Cl + off + 2) = __halves2half2(l2, l3);
        } else if (EPI == 1) {
            float rm = rs[row0 + row];
            v.x = tanhf(v.x) * rm * cs[col0 + lane * 4 + 0];
            v.y = tanhf(v.y) * rm * cs[col0 + lane * 4 + 1];
            v.z = tanhf(v.z) * rm * cs[col0 + lane * 4 + 2];
            v.w = tanhf(v.w) * rm * cs[col0 + lane * 4 + 3];
            *(float4*)(Cs + row * CSLD + lane * 4) = v;   // for transposed pass
            size_t off = (size_t)(row0 + row) * ldc + col0 + lane * 4;
            *(__half2*)(Ch + off)     = __halves2half2(__float2half_rn(v.x), __float2half_rn(v.y));
            *(__half2*)(Ch + off + 2) = __halves2half2(__float2half_rn(v.z), __float2half_rn(v.w));
        } else if (EPI == 3) {
            v.x = fmaxf(v.x + bias[col0 + lane * 4 + 0], 0.f);
            v.y = fmaxf(v.y + bias[col0 + lane * 4 + 1], 0.f);
            v.z = fmaxf(v.z + bias[col0 + lane * 4 + 2], 0.f);
            v.w = fmaxf(v.w + bias[col0 + lane * 4 + 3], 0.f);
            *(float4*)(Cf + (size_t)(row0 + row) * ldc + col0 + lane * 4) = v;
        } else if (EPI == 4) {
            size_t off = (size_t)(row0 + row) * ldc + col0 + lane * 4;
            *(__half2*)(Ch + off)     = __halves2half2(__float2half_rn(v.x), __float2half_rn(v.y));
            *(__half2*)(Ch + off + 2) = __halves2half2(__float2half_rn(v.z), __float2half_rn(v.w));
        } else {   // EPI == 5: relu -> fp16 (max commutes with rn: pool identical)
            v.x = fmaxf(v.x, 0.f); v.y = fmaxf(v.y, 0.f);
            v.z = fmaxf(v.z, 0.f); v.w = fmaxf(v.w, 0.f);
            size_t off = (size_t)(row0 + row) * ldc + col0 + lane * 4;
            *(__half2*)(Ch + off)     = __halves2half2(__float2half_rn(v.x), __float2half_rn(v.y));
            *(__half2*)(Ch + off + 2) = __halves2half2(__float2half_rn(v.z), __float2half_rn(v.w));
        }
    }

    if (EPI == 1) {
        __syncthreads();
        #pragma unroll
        for (int ct = 0; ct < 32; ct++) {
            int col = ct * 4 + wid;
            #pragma unroll
            for (int cc = 0; cc < 4; cc++) {
                int r = cc * 32 + lane;
                float x = Cs[r * CSLD + col];
                CTh[(size_t)(col0 + col) * ldct + row0 + r] = __float2half_rn(x);
            }
        }
    }
}

// smem sizes
#define SM_P3 (2 * 4 * (128 * 40 * 2))   // 81920  (3-pass, KCH=32, 2 CTA/SM)
#define SM_P2 (2 * 3 * (128 * 72 * 2))   // 110592 (2-pass, KCH=64, 2 CTA/SM)
#define SM_P1 (2 * 2 * (128 * 72 * 2))   // 73728  (1-pass, KCH=64, 2 CTA/SM)

// ---------------- GEMM kernels ------------------------------------------------
__global__ __launch_bounds__(NTHR, 2) void k_pw() {
    int bh = blockIdx.z;
    gemm_core<3, 32, 0, 0>(g_Ph + (size_t)(bh >> 3) * L1c * Dc,
                           g_Pl + (size_t)(bh >> 3) * L1c * Dc, nullptr, nullptr,
                           g_WaffTh + (size_t)(bh & 7) * Dc * Dc,
                           g_WaffTl + (size_t)(bh & 7) * Dc * Dc,
                           nullptr, g_Th + (size_t)bh * L1c * Dc,
                           g_Tl + (size_t)bh * L1c * Dc,
                           nullptr, 0,
                           Dc, Dc, Dc, Dc, nullptr, nullptr, nullptr);
}
// batch-split: bh = blockIdx.z + zb
__global__ __launch_bounds__(NTHR, 2) void k_aff(const float* __restrict__ pm,
                                                 const float* __restrict__ sm_,
                                                 int zb) {
    int bh = blockIdx.z + zb, b = bh >> 3;
    gemm_core<3, 32, 0, 1>(g_Th + (size_t)bh * L1c * Dc,
                           g_Tl + (size_t)bh * L1c * Dc, nullptr, nullptr,
                           g_Sh + (size_t)b * L2c * Dc,
                           g_Sl + (size_t)b * L2c * Dc,
                           nullptr,
                           g_affh + (size_t)bh * L1c * L2c, nullptr,
                           g_affTh + (size_t)bh * L2c * L1c, L1c,
                           Dc, Dc, Dc, L2c,
                           pm + b * L1c, sm_ + b * L2c, nullptr);
}
__global__ __launch_bounds__(NTHR, 2) void k_proj() {
    int b = blockIdx.z >> 1, sel = blockIdx.z & 1;
    const __half* Wh = sel ? g_WsTh : g_WpTh;
    const __half* Wl = sel ? g_WsTl : g_WpTl;
    const __half* Xh = (sel ? g_Sh : g_Ph) + (size_t)b * L1c * Dc;
    __half* Oh = (sel ? g_PSTh : g_PPTh) + (size_t)b * INNERc * L1c;
    gemm_core<2, 64, 0, 4>(Wh, Wl, nullptr, nullptr, Xh, nullptr,
                           nullptr, Oh, nullptr, nullptr, 0,
                           Dc, Dc, Dc, L1c, nullptr, nullptr, nullptr);
}
// batch-split: bh = (blockIdx.z >> 1) + bhb
__global__ __launch_bounds__(NTHR, 2) void k_wpws(int bhb) {
    int bh = (blockIdx.z >> 1) + bhb, sel = blockIdx.z & 1;
    int b = bh >> 3, h = bh & 7;
    const __half *Ah_, *Bh_;
    __half* Ch_;
    if (sel == 0) {
        Ah_ = g_affTh + (size_t)bh * L2c * L1c;
        Bh_ = g_PPTh + (size_t)b * INNERc * L1c + (size_t)h * HDc * L1c;
        Ch_ = g_wph + (size_t)bh * L2c * HDc;
    } else {
        Ah_ = g_affh + (size_t)bh * L1c * L2c;
        Bh_ = g_PSTh + (size_t)b * INNERc * L2c + (size_t)h * HDc * L2c;
        Ch_ = g_wsh + (size_t)bh * L1c * HDc;
    }
    gemm_core<1, 64, 0, 5>(Ah_, nullptr, nullptr, nullptr, Bh_, nullptr,
                           nullptr, Ch_, nullptr, nullptr, 0,
                           L1c, L1c, L1c, HDc, nullptr, nullptr, nullptr);
}
// batch-split: b = (blockIdx.z >> 1) + bb
__global__ __launch_bounds__(NTHR, 2) void k_ffn(const float* __restrict__ bfp,
                                                 const float* __restrict__ bfs,
                                                 float* __restrict__ Op,
                                                 float* __restrict__ Os,
                                                 int bb) {
    int b = (blockIdx.z >> 1) + bb, sel = blockIdx.z & 1;
    const __half* Xh = (sel ? g_Sh : g_Ph) + (size_t)b * L1c * Dc;
    const __half* ph = (sel ? g_poolph : g_poolsh) + (size_t)b * L1c * HDc;
    const __half* Wh = sel ? g_WfsTh : g_WfpTh;
    const float* bias = sel ? bfs : bfp;
    float* O = (sel ? Os : Op) + (size_t)b * L1c * Dc;
    gemm_core<1, 64, 1, 3>(Xh, nullptr, ph, nullptr, Wh, nullptr,
                           O, nullptr, nullptr, nullptr, 0,
                           DCc, Dc, DCc, Dc, nullptr, nullptr, bias);
}

// ---------------- conversion kernels ------------------------------------------
__global__ void k_split2(const float* __restrict__ X0, __half* __restrict__ H0, __half* __restrict__ L0,
                         const float* __restrict__ X1, __half* __restrict__ H1, __half* __restrict__ L1,
                         int n) {
    const float* X = blockIdx.y ? X1 : X0;
    __half* H = blockIdx.y ? H1 : H0;
    __half* L = blockIdx.y ? L1 : L0;
    int i = (blockIdx.x * blockDim.x + threadIdx.x) * 4;
    if (i >= n) return;
    float4 v = *(const float4*)(X + i);
    __half h0, h1, h2, h3, l0, l1, l2, l3;
    split2(v.x, h0, l0); split2(v.y, h1, l1);
    split2(v.z, h2, l2); split2(v.w, h3, l3);
    *(__half2*)(H + i)     = __halves2half2(h0, h1);
    *(__half2*)(H + i + 2) = __halves2half2(h2, h3);
    *(__half2*)(L + i)     = __halves2half2(l0, l1);
    *(__half2*)(L + i + 2) = __halves2half2(l2, l3);
}

__global__ void k_splitT(const float* __restrict__ X,
                         __half* __restrict__ H, __half* __restrict__ L,
                         int R, int C) {
    __shared__ float t[32][33];
    int z = blockIdx.z;
    int x0 = blockIdx.x * 32;
    int y0 = blockIdx.y * 32;
    const float* Xz = X + (size_t)z * R * C;
    #pragma unroll
    for (int i = 0; i < 4; i++) {
        int r = y0 + threadIdx.y * 4 + i;
        t[threadIdx.y * 4 + i][threadIdx.x] = Xz[(size_t)r * C + x0 + threadIdx.x];
    }
    __syncthreads();
    size_t zb = (size_t)z * R * C;
    #pragma unroll
    for (int i = 0; i < 4; i++) {
        int oc = x0 + threadIdx.y * 4 + i;
        float v = t[threadIdx.x][threadIdx.y * 4 + i];
        __half h, l;
        split2(v, h, l);
        H[zb + (size_t)oc * R + y0 + threadIdx.x] = h;
        L[zb + (size_t)oc * R + y0 + threadIdx.x] = l;
    }
}

__global__ void k_splitT4(const float* __restrict__ Wp,  __half* __restrict__ WpH,  __half* __restrict__ WpL,
                          const float* __restrict__ Ws,  __half* __restrict__ WsH,  __half* __restrict__ WsL,
                          const float* __restrict__ Wfp, __half* __restrict__ WfpH,
                          const float* __restrict__ Wfs, __half* __restrict__ WfsH) {
    __shared__ float t[32][33];
    int z = blockIdx.z;
    int R = (z < 2) ? Dc : DCc;
    int C = (z < 2) ? INNERc : Dc;
    if ((int)blockIdx.x * 32 >= C || (int)blockIdx.y * 32 >= R) return;
    const float* X = (z == 0) ? Wp : (z == 1) ? Ws : (z == 2) ? Wfp : Wfs;
    __half* H = (z == 0) ? WpH : (z == 1) ? WsH : (z == 2) ? WfpH : WfsH;
    __half* L = (z == 0) ? WpL : (z == 1) ? WsL : nullptr;
    int x0 = blockIdx.x * 32;
    int y0 = blockIdx.y * 32;
    #pragma unroll
    for (int i = 0; i < 4; i++) {
        int r = y0 + threadIdx.y * 4 + i;
        t[threadIdx.y * 4 + i][threadIdx.x] = X[(size_t)r * C + x0 + threadIdx.x];
    }
    __syncthreads();
    #pragma unroll
    for (int i = 0; i < 4; i++) {
        int oc = x0 + threadIdx.y * 4 + i;
        float v = t[threadIdx.x][threadIdx.y * 4 + i];
        __half h, l;
        split2(v, h, l);
        H[(size_t)oc * R + y0 + threadIdx.x] = h;
        if (z < 2) L[(size_t)oc * R + y0 + threadIdx.x] = l;
    }
}

// ---------------- pools (fp16 in, batch-split) ---------------------------------
__global__ void k_pool2(int bb) {
    int idx = blockIdx.x * blockDim.x + threadIdx.x;
    const int tot = 8 * L2c * HDc;          // half the batches per launch
    if (idx >= tot) return;
    int bl = idx / (L2c * HDc);
    int r  = idx - bl * (L2c * HDc);
    int b  = bl + bb;
    if (blockIdx.y == 0) {
        __half m = g_wph[((size_t)b * Hc) * L2c * HDc + r];
        #pragma unroll
        for (int h = 1; h < Hc; h++)
            m = __hmax(m, g_wph[((size_t)(b * Hc + h)) * L2c * HDc + r]);
        g_poolph[(size_t)b * L2c * HDc + r] = m;
    } else {
        __half m = g_wsh[((size_t)b * Hc) * L1c * HDc + r];
        #pragma unroll
        for (int h = 1; h < Hc; h++)
            m = __hmax(m, g_wsh[((size_t)(b * Hc + h)) * L1c * HDc + r]);
        g_poolsh[(size_t)b * L1c * HDc + r] = m;
    }
}

// ---------------- launcher -----------------------------------------------------
template<typename T>
static T* sym_addr(const void* sym) {
    void* p = nullptr;
    cudaGetSymbolAddress(&p, sym);
    return (T*)p;
}

extern "C" void kernel_launch(void* const* d_in, const int* in_sizes, int n_in,
                              void* d_out, int out_size) {
    const float* P    = (const float*)d_in[0];
    const float* S    = (const float*)d_in[1];
    const float* pm   = (const float*)d_in[2];
    const float* sm   = (const float*)d_in[3];
    const float* Waff = (const float*)d_in[4];
    const float* Wp   = (const float*)d_in[5];
    const float* Ws   = (const float*)d_in[6];
    const float* Wfp  = (const float*)d_in[7];
    const float* bfp  = (const float*)d_in[8];
    const float* Wfs  = (const float*)d_in[9];
    const float* bfs  = (const float*)d_in[10];

    float* outp = (float*)d_out;
    float* outs = outp + (size_t)Bc * L1c * Dc;

    __half* Ph     = sym_addr<__half>(g_Ph);
    __half* Pl     = sym_addr<__half>(g_Pl);
    __half* Sh     = sym_addr<__half>(g_Sh);
    __half* Sl     = sym_addr<__half>(g_Sl);
    __half* WaffTh = sym_addr<__half>(g_WaffTh);
    __half* WaffTl = sym_addr<__half>(g_WaffTl);
    __half* WpTh   = sym_addr<__half>(g_WpTh);
    __half* WpTl   = sym_addr<__half>(g_WpTl);
    __half* WsTh   = sym_addr<__half>(g_WsTh);
    __half* WsTl   = sym_addr<__half>(g_WsTl);
    __half* WfpTh  = sym_addr<__half>(g_WfpTh);
    __half* WfsTh  = sym_addr<__half>(g_WfsTh);

    cudaFuncSetAttribute(k_pw,   cudaFuncAttributeMaxDynamicSharedMemorySize, SM_P3);
    cudaFuncSetAttribute(k_aff,  cudaFuncAttributeMaxDynamicSharedMemorySize, SM_P3);
    cudaFuncSetAttribute(k_proj, cudaFuncAttributeMaxDynamicSharedMemorySize, SM_P2);
    cudaFuncSetAttribute(k_wpws, cudaFuncAttributeMaxDynamicSharedMemorySize, SM_P1);
    cudaFuncSetAttribute(k_ffn,  cudaFuncAttributeMaxDynamicSharedMemorySize, SM_P1);

    static cudaStream_t s_side = nullptr;
    static cudaEvent_t  ev_fork = nullptr, ev_aff0 = nullptr, ev_join = nullptr;
    static int stream_ok = -1;
    if (stream_ok < 0) {
        stream_ok = (cudaStreamCreateWithFlags(&s_side, cudaStreamNonBlocking) == cudaSuccess &&
                     cudaEventCreateWithFlags(&ev_fork, cudaEventDisableTiming) == cudaSuccess &&
                     cudaEventCreateWithFlags(&ev_aff0, cudaEventDisableTiming) == cudaSuccess &&
                     cudaEventCreateWithFlags(&ev_join, cudaEventDisableTiming) == cudaSuccess) ? 1 : 0;
    }

    dim3 blk(NTHR);
    const int HZ = Bc * Hc / 2;   // 64 bh per half

    if (stream_ok) {
        // ---- main: splits, pw, aff halves ------------------------------------
        { int n = Bc * L1c * Dc; k_split2<<<dim3(n / 1024, 2), 256>>>(P, Ph, Pl, S, Sh, Sl, n); }
        cudaEventRecord(ev_fork, 0);
        k_splitT<<<dim3(Dc / 32, Dc / 32, Hc), dim3(32, 8)>>>(Waff, WaffTh, WaffTl, Dc, Dc);
        k_pw  <<<dim3(4, 4, Bc * Hc), blk, SM_P3>>>();
        k_aff <<<dim3(4, 4, HZ), blk, SM_P3>>>(pm, sm, 0);     // aff half 0
        cudaEventRecord(ev_aff0, 0);
        k_aff <<<dim3(4, 4, HZ), blk, SM_P3>>>(pm, sm, HZ);    // aff half 1

        // ---- side: weights+proj under pw; tail half-0 under aff half-1 -------
        cudaStreamWaitEvent(s_side, ev_fork, 0);
        k_splitT4<<<dim3(INNERc / 32, DCc / 32, 4), dim3(32, 8), 0, s_side>>>(
            Wp, WpTh, WpTl, Ws, WsTh, WsTl, Wfp, WfpTh, Wfs, WfsTh);
        k_proj<<<dim3(4, 8, Bc * 2), blk, SM_P2, s_side>>>();
        cudaStreamWaitEvent(s_side, ev_aff0, 0);
        k_wpws<<<dim3(1, 4, HZ * 2), blk, SM_P1, s_side>>>(0);
        { int tot = 8 * L2c * HDc; k_pool2<<<dim3((tot + 255) / 256, 2), 256, 0, s_side>>>(0); }
        k_ffn <<<dim3(4, 4, Bc), blk, SM_P1, s_side>>>(bfp, bfs, outp, outs, 0);
        cudaEventRecord(ev_join, s_side);

        // ---- main: tail half-1 after join ------------------------------------
        cudaStreamWaitEvent(0, ev_join, 0);
        k_wpws<<<dim3(1, 4, HZ * 2), blk, SM_P1>>>(HZ);
        { int tot = 8 * L2c * HDc; k_pool2<<<dim3((tot + 255) / 256, 2), 256>>>(8); }
        k_ffn <<<dim3(4, 4, Bc), blk, SM_P1>>>(bfp, bfs, outp, outs, 8);
    } else {
        // serial fallback
        { int n = Bc * L1c * Dc; k_split2<<<dim3(n / 1024, 2), 256>>>(P, Ph, Pl, S, Sh, Sl, n); }
        k_splitT<<<dim3(Dc / 32, Dc / 32, Hc), dim3(32, 8)>>>(Waff, WaffTh, WaffTl, Dc, Dc);
        k_splitT4<<<dim3(INNERc / 32, DCc / 32, 4), dim3(32, 8)>>>(
            Wp, WpTh, WpTl, Ws, WsTh, WsTl, Wfp, WfpTh, Wfs, WfsTh);
        k_pw  <<<dim3(4, 4, Bc * Hc), blk, SM_P3>>>();
        k_aff <<<dim3(4, 4, HZ), blk, SM_P3>>>(pm, sm, 0);
        k_aff <<<dim3(4, 4, HZ), blk, SM_P3>>>(pm, sm, HZ);
        k_proj<<<dim3(4, 8, Bc * 2), blk, SM_P2>>>();
        k_wpws<<<dim3(1, 4, HZ * 2), blk, SM_P1>>>(0);
        k_wpws<<<dim3(1, 4, HZ * 2), blk, SM_P1>>>(HZ);
        { int tot = 8 * L2c * HDc; k_pool2<<<dim3((tot + 255) / 256, 2), 256>>>(0); }
        { int tot = 8 * L2c * HDc; k_pool2<<<dim3((tot + 255) / 256, 2), 256>>>(8); }
        k_ffn <<<dim3(4, 4, Bc), blk, SM_P1>>>(bfp, bfs, outp, outs, 0);
        k_ffn <<<dim3(4, 4, Bc), blk, SM_P1>>>(bfp, bfs, outp, outs, 8);
    }
}

// round 16
// speedup vs baseline: 1.1318x; 1.0431x over previous
#include <cuda_runtime.h>
#include <cuda_fp16.h>
#include <mma.h>
#include <math.h>
#include <stdint.h>

using namespace nvcuda;

// Problem constants
#define Bc     16
#define L1c    512
#define L2c    512
#define Dc     512
#define Hc     8
#define INNERc 1024
#define HDc    128
#define DCc    640   // D + HD

// ---------------- fp16 hi/lo pair scratch (static device globals) -------------
__device__ __align__(256) __half g_Ph [(size_t)Bc*L1c*Dc];
__device__ __align__(256) __half g_Pl [(size_t)Bc*L1c*Dc];
__device__ __align__(256) __half g_Sh [(size_t)Bc*L2c*Dc];
__device__ __align__(256) __half g_Sl [(size_t)Bc*L2c*Dc];
__device__ __align__(256) __half g_WaffTh[(size_t)Hc*Dc*Dc];
__device__ __align__(256) __half g_WaffTl[(size_t)Hc*Dc*Dc];
__device__ __align__(256) __half g_WpTh[(size_t)INNERc*Dc];
__device__ __align__(256) __half g_WpTl[(size_t)INNERc*Dc];
__device__ __align__(256) __half g_WsTh[(size_t)INNERc*Dc];
__device__ __align__(256) __half g_WsTl[(size_t)INNERc*Dc];
__device__ __align__(256) __half g_WfpTh[(size_t)Dc*DCc];
__device__ __align__(256) __half g_WfsTh[(size_t)Dc*DCc];
__device__ __align__(256) __half g_Th  [(size_t)Bc*Hc*L1c*Dc];
__device__ __align__(256) __half g_Tl  [(size_t)Bc*Hc*L1c*Dc];
__device__ __align__(256) __half g_affh [(size_t)Bc*Hc*L1c*L2c];
__device__ __align__(256) __half g_affTh[(size_t)Bc*Hc*L2c*L1c];
__device__ __align__(256) __half g_PPTh[(size_t)Bc*INNERc*L1c];
__device__ __align__(256) __half g_PSTh[(size_t)Bc*INNERc*L2c];
__device__ __align__(256) __half g_wph[(size_t)Bc*Hc*L2c*HDc];
__device__ __align__(256) __half g_wsh[(size_t)Bc*Hc*L1c*HDc];
__device__ __align__(256) __half g_poolph[(size_t)Bc*L2c*HDc];
__device__ __align__(256) __half g_poolsh[(size_t)Bc*L1c*HDc];

// ---------------- helpers -----------------------------------------------------
__device__ __forceinline__ uint32_t smem_u32(const void* p) {
    uint32_t a;
    asm("{ .reg .u64 t; cvta.to.shared.u64 t, %1; cvt.u32.u64 %0, t; }" : "=r"(a) : "l"(p));
    return a;
}
__device__ __forceinline__ void cpa16(uint32_t dst, const void* src) {
    asm volatile("cp.async.cg.shared.global [%0], [%1], 16;" :: "r"(dst), "l"(src));
}
__device__ __forceinline__ void cpa_commit() { asm volatile("cp.async.commit_group;" ::: "memory"); }
__device__ __forceinline__ void cpa_wait0()  { asm volatile("cp.async.wait_group 0;" ::: "memory"); }

__device__ __forceinline__ void split2(float x, __half& h, __half& l) {
    h = __float2half_rn(x);
    l = __float2half_rn(x - __half2float(h));
}

#define CSLD 132
#define NTHR 128   // 4 warps, 2x2 of 64x64 warp tiles

// ---- staging: global fp16 rows -> smem tile (128 rows x KCH halves) ----------
template<int KCH, int MODE>
__device__ __forceinline__ void stage16(const __half* __restrict__ G, int ld,
                                        const __half* __restrict__ pool,
                                        int rb, int k0, uint32_t dst) {
    constexpr int RPR = KCH / 8;
    constexpr int IT  = 128 * RPR / NTHR;
    const int tid = threadIdx.x;
    #pragma unroll
    for (int r = 0; r < IT; r++) {
        int idx = r * NTHR + tid;
        int m   = idx / RPR;
        int kq  = (idx % RPR) * 8;
        const __half* src;
        if (MODE == 0) {
            src = G + (size_t)(rb + m) * ld + k0 + kq;
        } else {
            int gk = k0 + kq;
            src = (gk < Dc) ? G    + (size_t)(rb + m) * Dc  + gk
                            : pool + (size_t)(rb + m) * HDc + (gk - Dc);
        }
        cpa16(dst + m * ((KCH + 8) * 2) + kq * 2, src);
    }
}

typedef wmma::fragment<wmma::matrix_a, 16, 16, 16, __half, wmma::row_major> FragA;
typedef wmma::fragment<wmma::matrix_b, 16, 16, 16, __half, wmma::col_major> FragB;
typedef wmma::fragment<wmma::accumulator, 16, 16, 16, float> FragC;

// ---------------- core GEMM (round-12 known-good: 2-stage, 1 sync/chunk) -------
template<int PASSES, int KCH, int AMODE, int EPI>
__device__ __forceinline__ void gemm_core(
    const __half* __restrict__ Ah_g, const __half* __restrict__ Al_g,
    const __half* __restrict__ aph,  const __half* __restrict__ apl,
    const __half* __restrict__ Bh_g, const __half* __restrict__ Bl_g,
    float* __restrict__ Cf, __half* __restrict__ Ch, __half* __restrict__ Cl,
    __half* __restrict__ CTh, int ldct,
    int K, int lda, int ldb, int ldc,
    const float* __restrict__ rs, const float* __restrict__ cs,
    const float* __restrict__ bias)
{
    constexpr int TLD   = KCH + 8;
    constexpr int TILEB = 128 * TLD * 2;
    constexpr int NT    = PASSES + 1;
    constexpr int BUFB  = NT * TILEB;
    constexpr int BOFF  = (PASSES >= 2) ? 2 : 1;

    extern __shared__ char smc[];
    const uint32_t smb = smem_u32(smc);

    const int tid  = threadIdx.x;
    const int wid  = tid >> 5;
    const int lane = tid & 31;
    const int wm   = wid & 1;
    const int wn   = wid >> 1;
    const int row0 = blockIdx.y * 128;
    const int col0 = blockIdx.x * 128;

    FragC acc[4][4];
    #pragma unroll
    for (int i = 0; i < 4; i++)
        #pragma unroll
        for (int j = 0; j < 4; j++) wmma::fill_fragment(acc[i][j], 0.0f);

    const int NCH = K / KCH;

    {
        stage16<KCH, AMODE>(Ah_g, lda, aph, row0, 0, smb);
        if (PASSES >= 2)
            stage16<KCH, AMODE>(Al_g, lda, apl, row0, 0, smb + TILEB);
        stage16<KCH, 0>(Bh_g, ldb, nullptr, col0, 0, smb + BOFF * TILEB);
        if (PASSES == 3)
            stage16<KCH, 0>(Bl_g, ldb, nullptr, col0, 0, smb + 3 * TILEB);
        cpa_commit();
    }

    for (int c = 0; c < NCH; c++) {
        cpa_wait0();
        __syncthreads();
        if (c + 1 < NCH) {
            uint32_t nb = smb + ((c + 1) & 1) * BUFB;
            int k0 = (c + 1) * KCH;
            stage16<KCH, AMODE>(Ah_g, lda, aph, row0, k0, nb);
            if (PASSES >= 2)
                stage16<KCH, AMODE>(Al_g, lda, apl, row0, k0, nb + TILEB);
            stage16<KCH, 0>(Bh_g, ldb, nullptr, col0, k0, nb + BOFF * TILEB);
            if (PASSES == 3)
                stage16<KCH, 0>(Bl_g, ldb, nullptr, col0, k0, nb + 3 * TILEB);
            cpa_commit();
        } else {
            cpa_commit();
        }

        const __half* Ahs = (const __half*)(smc + (c & 1) * BUFB);
        const __half* Als = Ahs + TILEB / 2;
        const __half* Bhs = Ahs + BOFF * (TILEB / 2);
        const __half* Bls = Ahs + 3 * (TILEB / 2);

        #pragma unroll
        for (int ks = 0; ks < KCH / 16; ks++) {
            FragA fah[4], fal[4];
            #pragma unroll
            for (int ti = 0; ti < 4; ti++) {
                int ro = (wm * 64 + ti * 16) * TLD + ks * 16;
                wmma::load_matrix_sync(fah[ti], Ahs + ro, TLD);
                if (PASSES >= 2)
                    wmma::load_matrix_sync(fal[ti], Als + ro, TLD);
            }
            #pragma unroll
            for (int tj = 0; tj < 4; tj++) {
                int co = (wn * 64 + tj * 16) * TLD + ks * 16;
                {
                    FragB fbh;
                    wmma::load_matrix_sync(fbh, Bhs + co, TLD);
                    #pragma unroll
                    for (int ti = 0; ti < 4; ti++) {
                        wmma::mma_sync(acc[ti][tj], fah[ti], fbh, acc[ti][tj]);
                        if (PASSES >= 2)
                            wmma::mma_sync(acc[ti][tj], fal[ti], fbh, acc[ti][tj]);
                    }
                }
                if (PASSES == 3) {
                    FragB fbl;
                    wmma::load_matrix_sync(fbl, Bls + co, TLD);
                    #pragma unroll
                    for (int ti = 0; ti < 4; ti++)
                        wmma::mma_sync(acc[ti][tj], fah[ti], fbl, acc[ti][tj]);
                }
            }
        }
    }
    __syncthreads();

    // ---------------- epilogue through smem -----------------------------------
    float* Cs = (float*)smc;
    #pragma unroll
    for (int ti = 0; ti < 4; ti++)
        #pragma unroll
        for (int tj = 0; tj < 4; tj++)
            wmma::store_matrix_sync(Cs + (wm * 64 + ti * 16) * CSLD + wn * 64 + tj * 16,
                                    acc[ti][tj], CSLD, wmma::mem_row_major);
    __syncthreads();

    #pragma unroll
    for (int it = 0; it < 32; it++) {
        int row = it * 4 + wid;
        float4 v = *(float4*)(Cs + row * CSLD + lane * 4);
        if (EPI == 0) {
            __half h0, h1, h2, h3, l0, l1, l2, l3;
            split2(v.x, h0, l0); split2(v.y, h1, l1);
            split2(v.z, h2, l2); split2(v.w, h3, l3);
            size_t off = (size_t)(row0 + row) * ldc + col0 + lane * 4;
            *(__half2*)(Ch + off)     = __halves2half2(h0, h1);
            *(__half2*)(Ch + off + 2) = __halves2half2(h2, h3);
            *(__half2*)(Cl + off)     = __halves2half2(l0, l1);
            *(__half2*)(Cl + off + 2) = __halves2half2(l2, l3);
        } else if (EPI == 1) {
            float rm = rs[row0 + row];
            v.x = tanhf(v.x) * rm * cs[col0 + lane * 4 + 0];
            v.y = tanhf(v.y) * rm * cs[col0 + lane * 4 + 1];
            v.z = tanhf(v.z) * rm * cs[col0 + lane * 4 + 2];
            v.w = tanhf(v.w) * rm * cs[col0 + lane * 4 + 3];
            *(float4*)(Cs + row * CSLD + lane * 4) = v;
            size_t off = (size_t)(row0 + row) * ldc + col0 + lane * 4;
            *(__half2*)(Ch + off)     = __halves2half2(__float2half_rn(v.x), __float2half_rn(v.y));
            *(__half2*)(Ch + off + 2) = __halves2half2(__float2half_rn(v.z), __float2half_rn(v.w));
        } else if (EPI == 3) {
            v.x = fmaxf(v.x + bias[col0 + lane * 4 + 0], 0.f);
            v.y = fmaxf(v.y + bias[col0 + lane * 4 + 1], 0.f);
            v.z = fmaxf(v.z + bias[col0 + lane * 4 + 2], 0.f);
            v.w = fmaxf(v.w + bias[col0 + lane * 4 + 3], 0.f);
            *(float4*)(Cf + (size_t)(row0 + row) * ldc + col0 + lane * 4) = v;
        } else if (EPI == 4) {
            size_t off = (size_t)(row0 + row) * ldc + col0 + lane * 4;
            *(__half2*)(Ch + off)     = __halves2half2(__float2half_rn(v.x), __float2half_rn(v.y));
            *(__half2*)(Ch + off + 2) = __halves2half2(__float2half_rn(v.z), __float2half_rn(v.w));
        } else {   // EPI == 5: relu -> fp16
            v.x = fmaxf(v.x, 0.f); v.y = fmaxf(v.y, 0.f);
            v.z = fmaxf(v.z, 0.f); v.w = fmaxf(v.w, 0.f);
            size_t off = (size_t)(row0 + row) * ldc + col0 + lane * 4;
            *(__half2*)(Ch + off)     = __halves2half2(__float2half_rn(v.x), __float2half_rn(v.y));
            *(__half2*)(Ch + off + 2) = __halves2half2(__float2half_rn(v.z), __float2half_rn(v.w));
        }
    }

    if (EPI == 1) {
        __syncthreads();
        #pragma unroll
        for (int ct = 0; ct < 32; ct++) {
            int col = ct * 4 + wid;
            #pragma unroll
            for (int cc = 0; cc < 4; cc++) {
                int r = cc * 32 + lane;
                float x = Cs[r * CSLD + col];
                CTh[(size_t)(col0 + col) * ldct + row0 + r] = __float2half_rn(x);
            }
        }
    }
}

// smem sizes
#define SM_P3 (2 * 4 * (128 * 40 * 2))   // 81920
#define SM_P2 (2 * 3 * (128 * 72 * 2))   // 110592
#define SM_P1 (2 * 2 * (128 * 72 * 2))   // 73728

// ---------------- GEMM kernels (all batch-split capable) -----------------------
__global__ __launch_bounds__(NTHR, 2) void k_pw(int zb) {
    int bh = blockIdx.z + zb;
    gemm_core<3, 32, 0, 0>(g_Ph + (size_t)(bh >> 3) * L1c * Dc,
                           g_Pl + (size_t)(bh >> 3) * L1c * Dc, nullptr, nullptr,
                           g_WaffTh + (size_t)(bh & 7) * Dc * Dc,
                           g_WaffTl + (size_t)(bh & 7) * Dc * Dc,
                           nullptr, g_Th + (size_t)bh * L1c * Dc,
                           g_Tl + (size_t)bh * L1c * Dc,
                           nullptr, 0,
                           Dc, Dc, Dc, Dc, nullptr, nullptr, nullptr);
}
__global__ __launch_bounds__(NTHR, 2) void k_aff(const float* __restrict__ pm,
                                                 const float* __restrict__ sm_,
                                                 int zb) {
    int bh = blockIdx.z + zb, b = bh >> 3;
    gemm_core<3, 32, 0, 1>(g_Th + (size_t)bh * L1c * Dc,
                           g_Tl + (size_t)bh * L1c * Dc, nullptr, nullptr,
                           g_Sh + (size_t)b * L2c * Dc,
                           g_Sl + (size_t)b * L2c * Dc,
                           nullptr,
                           g_affh + (size_t)bh * L1c * L2c, nullptr,
                           g_affTh + (size_t)bh * L2c * L1c, L1c,
                           Dc, Dc, Dc, L2c,
                           pm + b * L1c, sm_ + b * L2c, nullptr);
}
__global__ __launch_bounds__(NTHR, 2) void k_proj() {
    int b = blockIdx.z >> 1, sel = blockIdx.z & 1;
    const __half* Wh = sel ? g_WsTh : g_WpTh;
    const __half* Wl = sel ? g_WsTl : g_WpTl;
    const __half* Xh = (sel ? g_Sh : g_Ph) + (size_t)b * L1c * Dc;
    __half* Oh = (sel ? g_PSTh : g_PPTh) + (size_t)b * INNERc * L1c;
    gemm_core<2, 64, 0, 4>(Wh, Wl, nullptr, nullptr, Xh, nullptr,
                           nullptr, Oh, nullptr, nullptr, 0,
                           Dc, Dc, Dc, L1c, nullptr, nullptr, nullptr);
}
__global__ __launch_bounds__(NTHR, 2) void k_wpws(int bhb) {
    int bh = (blockIdx.z >> 1) + bhb, sel = blockIdx.z & 1;
    int b = bh >> 3, h = bh & 7;
    const __half *Ah_, *Bh_;
    __half* Ch_;
    if (sel == 0) {
        Ah_ = g_affTh + (size_t)bh * L2c * L1c;
        Bh_ = g_PPTh + (size_t)b * INNERc * L1c + (size_t)h * HDc * L1c;
        Ch_ = g_wph + (size_t)bh * L2c * HDc;
    } else {
        Ah_ = g_affh + (size_t)bh * L1c * L2c;
        Bh_ = g_PSTh + (size_t)b * INNERc * L2c + (size_t)h * HDc * L2c;
        Ch_ = g_wsh + (size_t)bh * L1c * HDc;
    }
    gemm_core<1, 64, 0, 5>(Ah_, nullptr, nullptr, nullptr, Bh_, nullptr,
                           nullptr, Ch_, nullptr, nullptr, 0,
                           L1c, L1c, L1c, HDc, nullptr, nullptr, nullptr);
}
__global__ __launch_bounds__(NTHR, 2) void k_ffn(const float* __restrict__ bfp,
                                                 const float* __restrict__ bfs,
                                                 float* __restrict__ Op,
                                                 float* __restrict__ Os,
                                                 int bb) {
    int b = (blockIdx.z >> 1) + bb, sel = blockIdx.z & 1;
    const __half* Xh = (sel ? g_Sh : g_Ph) + (size_t)b * L1c * Dc;
    const __half* ph = (sel ? g_poolph : g_poolsh) + (size_t)b * L1c * HDc;
    const __half* Wh = sel ? g_WfsTh : g_WfpTh;
    const float* bias = sel ? bfs : bfp;
    float* O = (sel ? Os : Op) + (size_t)b * L1c * Dc;
    gemm_core<1, 64, 1, 3>(Xh, nullptr, ph, nullptr, Wh, nullptr,
                           O, nullptr, nullptr, nullptr, 0,
                           DCc, Dc, DCc, Dc, nullptr, nullptr, bias);
}

// ---------------- conversion kernels ------------------------------------------
__global__ void k_split2(const float* __restrict__ X0, __half* __restrict__ H0, __half* __restrict__ L0,
                         const float* __restrict__ X1, __half* __restrict__ H1, __half* __restrict__ L1,
                         int n) {
    const float* X = blockIdx.y ? X1 : X0;
    __half* H = blockIdx.y ? H1 : H0;
    __half* L = blockIdx.y ? L1 : L0;
    int i = (blockIdx.x * blockDim.x + threadIdx.x) * 4;
    if (i >= n) return;
    float4 v = *(const float4*)(X + i);
    __half h0, h1, h2, h3, l0, l1, l2, l3;
    split2(v.x, h0, l0); split2(v.y, h1, l1);
    split2(v.z, h2, l2); split2(v.w, h3, l3);
    *(__half2*)(H + i)     = __halves2half2(h0, h1);
    *(__half2*)(H + i + 2) = __halves2half2(h2, h3);
    *(__half2*)(L + i)     = __halves2half2(l0, l1);
    *(__half2*)(L + i + 2) = __halves2half2(l2, l3);
}

__global__ void k_splitT(const float* __restrict__ X,
                         __half* __restrict__ H, __half* __restrict__ L,
                         int R, int C) {
    __shared__ float t[32][33];
    int z = blockIdx.z;
    int x0 = blockIdx.x * 32;
    int y0 = blockIdx.y * 32;
    const float* Xz = X + (size_t)z * R * C;
    #pragma unroll
    for (int i = 0; i < 4; i++) {
        int r = y0 + threadIdx.y * 4 + i;
        t[threadIdx.y * 4 + i][threadIdx.x] = Xz[(size_t)r * C + x0 + threadIdx.x];
    }
    __syncthreads();
    size_t zb = (size_t)z * R * C;
    #pragma unroll
    for (int i = 0; i < 4; i++) {
        int oc = x0 + threadIdx.y * 4 + i;
        float v = t[threadIdx.x][threadIdx.y * 4 + i];
        __half h, l;
        split2(v, h, l);
        H[zb + (size_t)oc * R + y0 + threadIdx.x] = h;
        L[zb + (size_t)oc * R + y0 + threadIdx.x] = l;
    }
}

__global__ void k_splitT4(const float* __restrict__ Wp,  __half* __restrict__ WpH,  __half* __restrict__ WpL,
                          const float* __restrict__ Ws,  __half* __restrict__ WsH,  __half* __restrict__ WsL,
                          const float* __restrict__ Wfp, __half* __restrict__ WfpH,
                          const float* __restrict__ Wfs, __half* __restrict__ WfsH) {
    __shared__ float t[32][33];
    int z = blockIdx.z;
    int R = (z < 2) ? Dc : DCc;
    int C = (z < 2) ? INNERc : Dc;
    if ((int)blockIdx.x * 32 >= C || (int)blockIdx.y * 32 >= R) return;
    const float* X = (z == 0) ? Wp : (z == 1) ? Ws : (z == 2) ? Wfp : Wfs;
    __half* H = (z == 0) ? WpH : (z == 1) ? WsH : (z == 2) ? WfpH : WfsH;
    __half* L = (z == 0) ? WpL : (z == 1) ? WsL : nullptr;
    int x0 = blockIdx.x * 32;
    int y0 = blockIdx.y * 32;
    #pragma unroll
    for (int i = 0; i < 4; i++) {
        int r = y0 + threadIdx.y * 4 + i;
        t[threadIdx.y * 4 + i][threadIdx.x] = X[(size_t)r * C + x0 + threadIdx.x];
    }
    __syncthreads();
    #pragma unroll
    for (int i = 0; i < 4; i++) {
        int oc = x0 + threadIdx.y * 4 + i;
        float v = t[threadIdx.x][threadIdx.y * 4 + i];
        __half h, l;
        split2(v, h, l);
        H[(size_t)oc * R + y0 + threadIdx.x] = h;
        if (z < 2) L[(size_t)oc * R + y0 + threadIdx.x] = l;
    }
}

// ---------------- pools (fp16 in, batch-split) ---------------------------------
__global__ void k_pool2(int bb) {
    int idx = blockIdx.x * blockDim.x + threadIdx.x;
    const int tot = 8 * L2c * HDc;
    if (idx >= tot) return;
    int bl = idx / (L2c * HDc);
    int r  = idx - bl * (L2c * HDc);
    int b  = bl + bb;
    if (blockIdx.y == 0) {
        __half m = g_wph[((size_t)b * Hc) * L2c * HDc + r];
        #pragma unroll
        for (int h = 1; h < Hc; h++)
            m = __hmax(m, g_wph[((size_t)(b * Hc + h)) * L2c * HDc + r]);
        g_poolph[(size_t)b * L2c * HDc + r] = m;
    } else {
        __half m = g_wsh[((size_t)b * Hc) * L1c * HDc + r];
        #pragma unroll
        for (int h = 1; h < Hc; h++)
            m = __hmax(m, g_wsh[((size_t)(b * Hc + h)) * L1c * HDc + r]);
        g_poolsh[(size_t)b * L1c * HDc + r] = m;
    }
}

// ---------------- launcher -----------------------------------------------------
template<typename T>
static T* sym_addr(const void* sym) {
    void* p = nullptr;
    cudaGetSymbolAddress(&p, sym);
    return (T*)p;
}

extern "C" void kernel_launch(void* const* d_in, const int* in_sizes, int n_in,
                              void* d_out, int out_size) {
    const float* P    = (const float*)d_in[0];
    const float* S    = (const float*)d_in[1];
    const float* pm   = (const float*)d_in[2];
    const float* sm   = (const float*)d_in[3];
    const float* Waff = (const float*)d_in[4];
    const float* Wp   = (const float*)d_in[5];
    const float* Ws   = (const float*)d_in[6];
    const float* Wfp  = (const float*)d_in[7];
    const float* bfp  = (const float*)d_in[8];
    const float* Wfs  = (const float*)d_in[9];
    const float* bfs  = (const float*)d_in[10];

    float* outp = (float*)d_out;
    float* outs = outp + (size_t)Bc * L1c * Dc;

    __half* Ph     = sym_addr<__half>(g_Ph);
    __half* Pl     = sym_addr<__half>(g_Pl);
    __half* Sh     = sym_addr<__half>(g_Sh);
    __half* Sl     = sym_addr<__half>(g_Sl);
    __half* WaffTh = sym_addr<__half>(g_WaffTh);
    __half* WaffTl = sym_addr<__half>(g_WaffTl);
    __half* WpTh   = sym_addr<__half>(g_WpTh);
    __half* WpTl   = sym_addr<__half>(g_WpTl);
    __half* WsTh   = sym_addr<__half>(g_WsTh);
    __half* WsTl   = sym_addr<__half>(g_WsTl);
    __half* WfpTh  = sym_addr<__half>(g_WfpTh);
    __half* WfsTh  = sym_addr<__half>(g_WfsTh);

    cudaFuncSetAttribute(k_pw,   cudaFuncAttributeMaxDynamicSharedMemorySize, SM_P3);
    cudaFuncSetAttribute(k_aff,  cudaFuncAttributeMaxDynamicSharedMemorySize, SM_P3);
    cudaFuncSetAttribute(k_proj, cudaFuncAttributeMaxDynamicSharedMemorySize, SM_P2);
    cudaFuncSetAttribute(k_wpws, cudaFuncAttributeMaxDynamicSharedMemorySize, SM_P1);
    cudaFuncSetAttribute(k_ffn,  cudaFuncAttributeMaxDynamicSharedMemorySize, SM_P1);

    // sA: HIGH priority (half-0 chain), sB: default (proj chain). Created once.
    static cudaStream_t sA = nullptr, sB = nullptr;
    static cudaEvent_t  ev_fork = nullptr, ev_proj = nullptr, ev_endA = nullptr;
    static int stream_ok = -1;
    if (stream_ok < 0) {
        int lo = 0, hi = 0;
        cudaDeviceGetStreamPriorityRange(&lo, &hi);   // hi = greatest priority
        stream_ok =
            (cudaStreamCreateWithPriority(&sA, cudaStreamNonBlocking, hi) == cudaSuccess &&
             cudaStreamCreateWithFlags(&sB, cudaStreamNonBlocking) == cudaSuccess &&
             cudaEventCreateWithFlags(&ev_fork, cudaEventDisableTiming) == cudaSuccess &&
             cudaEventCreateWithFlags(&ev_proj, cudaEventDisableTiming) == cudaSuccess &&
             cudaEventCreateWithFlags(&ev_endA, cudaEventDisableTiming) == cudaSuccess) ? 1 : 0;
    }

    dim3 blk(NTHR);
    const int HZ = Bc * Hc / 2;   // 64 bh per half

    if (stream_ok) {
        // main: input + Waff conversion, then fork
        { int n = Bc * L1c * Dc; k_split2<<<dim3(n / 1024, 2), 256>>>(P, Ph, Pl, S, Sh, Sl, n); }
        k_splitT<<<dim3(Dc / 32, Dc / 32, Hc), dim3(32, 8)>>>(Waff, WaffTh, WaffTl, Dc, Dc);
        cudaEventRecord(ev_fork, 0);

        // sA (high prio): half-0 compute front (pw0=slot3, aff0=slot4)
        cudaStreamWaitEvent(sA, ev_fork, 0);
        k_pw <<<dim3(4, 4, HZ), blk, SM_P3, sA>>>(0);
        k_aff<<<dim3(4, 4, HZ), blk, SM_P3, sA>>>(pm, sm, 0);

        // sB: weight transposes + proj (eligible from fork; fills pw idle)
        cudaStreamWaitEvent(sB, ev_fork, 0);
        k_splitT4<<<dim3(INNERc / 32, DCc / 32, 4), dim3(32, 8), 0, sB>>>(
            Wp, WpTh, WpTl, Ws, WsTh, WsTl, Wfp, WfpTh, Wfs, WfsTh);
        k_proj<<<dim3(4, 8, Bc * 2), blk, SM_P2, sB>>>();
        cudaEventRecord(ev_proj, sB);

        // sA: half-0 tail (high prio -> interleaves ahead of half-1 GEMMs)
        cudaStreamWaitEvent(sA, ev_proj, 0);
        k_wpws<<<dim3(1, 4, HZ * 2), blk, SM_P1, sA>>>(0);
        { int tot = 8 * L2c * HDc; k_pool2<<<dim3((tot + 255) / 256, 2), 256, 0, sA>>>(0); }
        k_ffn <<<dim3(4, 4, Bc), blk, SM_P1, sA>>>(bfp, bfs, outp, outs, 0);
        cudaEventRecord(ev_endA, sA);

        // main: half-1 chain
        k_pw <<<dim3(4, 4, HZ), blk, SM_P3>>>(HZ);
        k_aff<<<dim3(4, 4, HZ), blk, SM_P3>>>(pm, sm, HZ);
        cudaStreamWaitEvent(0, ev_proj, 0);
        k_wpws<<<dim3(1, 4, HZ * 2), blk, SM_P1>>>(HZ);
        { int tot = 8 * L2c * HDc; k_pool2<<<dim3((tot + 255) / 256, 2), 256>>>(8); }
        k_ffn <<<dim3(4, 4, Bc), blk, SM_P1>>>(bfp, bfs, outp, outs, 8);
        cudaStreamWaitEvent(0, ev_endA, 0);   // join
    } else {
        // serial fallback
        { int n = Bc * L1c * Dc; k_split2<<<dim3(n / 1024, 2), 256>>>(P, Ph, Pl, S, Sh, Sl, n); }
        k_splitT<<<dim3(Dc / 32, Dc / 32, Hc), dim3(32, 8)>>>(Waff, WaffTh, WaffTl, Dc, Dc);
        k_splitT4<<<dim3(INNERc / 32, DCc / 32, 4), dim3(32, 8)>>>(
            Wp, WpTh, WpTl, Ws, WsTh, WsTl, Wfp, WfpTh, Wfs, WfsTh);
        k_pw <<<dim3(4, 4, HZ), blk, SM_P3>>>(0);
        k_pw <<<dim3(4, 4, HZ), blk, SM_P3>>>(HZ);
        k_aff<<<dim3(4, 4, HZ), blk, SM_P3>>>(pm, sm, 0);
        k_aff<<<dim3(4, 4, HZ), blk, SM_P3>>>(pm, sm, HZ);
        k_proj<<<dim3(4, 8, Bc * 2), blk, SM_P2>>>();
        k_wpws<<<dim3(1, 4, HZ * 2), blk, SM_P1>>>(0);
        k_wpws<<<dim3(1, 4, HZ * 2), blk, SM_P1>>>(HZ);
        { int tot = 8 * L2c * HDc; k_pool2<<<dim3((tot + 255) / 256, 2), 256>>>(0); }
        { int tot = 8 * L2c * HDc; k_pool2<<<dim3((tot + 255) / 256, 2), 256>>>(8); }
        k_ffn <<<dim3(4, 4, Bc), blk, SM_P1>>>(bfp, bfs, outp, outs, 0);
        k_ffn <<<dim3(4, 4, Bc), blk, SM_P1>>>(bfp, bfs, outp, outs, 8);
    }
}